// round 2
// baseline (speedup 1.0000x reference)
#include <cuda_runtime.h>
#include <cuda_bf16.h>
#include <cstdint>

#define B_SZ 2
#define T_SZ 4096
#define D_MODEL 1024
#define D_STATE 16
#define D_CONV 4
#define D_INNER 2048
#define DT_RANK 64
#define NTOK (B_SZ * T_SZ)          // 8192
#define XDBC_W (DT_RANK + 2 * D_STATE)  // 96

// ---------------- scratch (device globals; no allocation allowed) ----------
__device__ float g_xn[NTOK * D_MODEL];          // 32 MB  rmsnorm output
__device__ float g_xr[NTOK * 2 * D_INNER];      // 128 MB x @ w_in (u | res)
__device__ float g_u[NTOK * D_INNER];           // 64 MB  conv+silu output
__device__ float g_xdbc[NTOK * XDBC_W];         // 3 MB   [dt | B | C]
__device__ float g_delta[NTOK * D_INNER];       // 64 MB
__device__ float g_y[NTOK * D_INNER];           // 64 MB  gated scan output

// ---------------- 1. RMSNorm -----------------------------------------------
__global__ void rmsnorm_kernel(const float* __restrict__ x,
                               const float* __restrict__ w) {
    int tok = blockIdx.x;
    const float* xp = x + (size_t)tok * D_MODEL;
    float s = 0.f;
    for (int i = threadIdx.x; i < D_MODEL; i += 256) {
        float v = xp[i];
        s += v * v;
    }
    __shared__ float red[8];
    #pragma unroll
    for (int o = 16; o > 0; o >>= 1) s += __shfl_down_sync(0xffffffffu, s, o);
    if ((threadIdx.x & 31) == 0) red[threadIdx.x >> 5] = s;
    __syncthreads();
    if (threadIdx.x < 8) {
        float v = red[threadIdx.x];
        #pragma unroll
        for (int o = 4; o > 0; o >>= 1) v += __shfl_down_sync(0xffu, v, o, 8);
        if (threadIdx.x == 0) red[0] = rsqrtf(v / (float)D_MODEL + 1e-5f);
    }
    __syncthreads();
    float rs = red[0];
    float* op = g_xn + (size_t)tok * D_MODEL;
    for (int i = threadIdx.x; i < D_MODEL; i += 256) op[i] = xp[i] * rs * w[i];
}

// ---------------- 2. tiled fp32 GEMM: C = A(MxK) * W(KxN) [+ resid] --------
#define BM 128
#define BN 128
#define BK 16
#define AS_STRIDE 132   // padded to break bank conflicts on transposed stores

__global__ __launch_bounds__(256, 2)
void gemm128(const float* __restrict__ A, const float* __restrict__ W,
             const float* __restrict__ resid, float* __restrict__ C,
             int M, int N, int K) {
    __shared__ float As[BK * AS_STRIDE];
    __shared__ float Bs[BK][BN];
    int tid = threadIdx.x;
    int bm = blockIdx.y * BM;
    int bn = blockIdx.x * BN;
    int tx = tid & 15, ty = tid >> 4;
    int row0 = ty * 8, col0 = tx * 8;
    float acc[8][8];
    #pragma unroll
    for (int i = 0; i < 8; i++)
        #pragma unroll
        for (int j = 0; j < 8; j++) acc[i][j] = 0.f;

    for (int k0 = 0; k0 < K; k0 += BK) {
        // A tile 128x16, stored transposed As[k][m]
        #pragma unroll
        for (int i = 0; i < 2; ++i) {
            int idx = tid + i * 256;
            int r = idx >> 2, c = (idx & 3) << 2;
            float4 v = *(const float4*)(A + (size_t)(bm + r) * K + k0 + c);
            As[(c + 0) * AS_STRIDE + r] = v.x;
            As[(c + 1) * AS_STRIDE + r] = v.y;
            As[(c + 2) * AS_STRIDE + r] = v.z;
            As[(c + 3) * AS_STRIDE + r] = v.w;
        }
        // B tile 16x128
        #pragma unroll
        for (int i = 0; i < 2; ++i) {
            int idx = tid + i * 256;
            int r = idx >> 5, c = (idx & 31) << 2;
            *(float4*)(&Bs[r][c]) = *(const float4*)(W + (size_t)(k0 + r) * N + bn + c);
        }
        __syncthreads();
        #pragma unroll
        for (int k = 0; k < BK; ++k) {
            float4 a0 = *(const float4*)(&As[k * AS_STRIDE + row0]);
            float4 a1 = *(const float4*)(&As[k * AS_STRIDE + row0 + 4]);
            float4 b0 = *(const float4*)(&Bs[k][col0]);
            float4 b1 = *(const float4*)(&Bs[k][col0 + 4]);
            float ra[8] = {a0.x, a0.y, a0.z, a0.w, a1.x, a1.y, a1.z, a1.w};
            float rb[8] = {b0.x, b0.y, b0.z, b0.w, b1.x, b1.y, b1.z, b1.w};
            #pragma unroll
            for (int i = 0; i < 8; i++)
                #pragma unroll
                for (int j = 0; j < 8; j++)
                    acc[i][j] = fmaf(ra[i], rb[j], acc[i][j]);
        }
        __syncthreads();
    }
    #pragma unroll
    for (int i = 0; i < 8; i++) {
        #pragma unroll
        for (int j = 0; j < 8; j += 4) {
            size_t off = (size_t)(bm + row0 + i) * N + bn + col0 + j;
            float4 v = make_float4(acc[i][j], acc[i][j + 1], acc[i][j + 2], acc[i][j + 3]);
            if (resid) {
                float4 r4 = *(const float4*)(resid + off);
                v.x += r4.x; v.y += r4.y; v.z += r4.z; v.w += r4.w;
            }
            *(float4*)(C + off) = v;
        }
    }
}

// ---------------- 3. depthwise causal conv (K=4) + bias + SiLU -------------
__global__ void conv_silu_kernel(const float* __restrict__ cw,
                                 const float* __restrict__ cb) {
    int idx = blockIdx.x * blockDim.x + threadIdx.x;
    if (idx >= NTOK * D_INNER) return;
    int d = idx & (D_INNER - 1);
    int tok = idx >> 11;
    int t = tok & (T_SZ - 1);
    float acc = cb[d];
    #pragma unroll
    for (int k = 0; k < D_CONV; ++k) {
        int tt = t - (D_CONV - 1) + k;
        if (tt >= 0)
            acc = fmaf(g_xr[(size_t)(tok - (D_CONV - 1) + k) * (2 * D_INNER) + d],
                       cw[d * D_CONV + k], acc);
    }
    g_u[idx] = acc / (1.f + __expf(-acc));
}

// ---------------- 4. xdbc = u @ w_x (2048 x 96) ----------------------------
__global__ void proj_x_kernel(const float* __restrict__ w_x) {
    __shared__ float us[D_INNER];
    int tok = blockIdx.x;
    for (int i = threadIdx.x; i < D_INNER; i += 96)
        us[i] = g_u[(size_t)tok * D_INNER + i];
    __syncthreads();
    int j = threadIdx.x;   // 0..95
    float a0 = 0.f, a1 = 0.f, a2 = 0.f, a3 = 0.f;
    #pragma unroll 4
    for (int k = 0; k < D_INNER; k += 4) {
        a0 = fmaf(us[k + 0], w_x[(k + 0) * XDBC_W + j], a0);
        a1 = fmaf(us[k + 1], w_x[(k + 1) * XDBC_W + j], a1);
        a2 = fmaf(us[k + 2], w_x[(k + 2) * XDBC_W + j], a2);
        a3 = fmaf(us[k + 3], w_x[(k + 3) * XDBC_W + j], a3);
    }
    g_xdbc[tok * XDBC_W + j] = (a0 + a1) + (a2 + a3);
}

// ---------------- 5. delta = softplus(dt @ w_dt + b_dt) --------------------
__global__ void delta_kernel(const float* __restrict__ w_dt,
                             const float* __restrict__ b_dt) {
    __shared__ float dts[DT_RANK];
    int tok = blockIdx.y;
    int col = blockIdx.x * 256 + threadIdx.x;
    if (threadIdx.x < DT_RANK) dts[threadIdx.x] = g_xdbc[tok * XDBC_W + threadIdx.x];
    __syncthreads();
    float acc = b_dt[col];
    #pragma unroll 16
    for (int k = 0; k < DT_RANK; ++k)
        acc = fmaf(dts[k], w_dt[k * D_INNER + col], acc);
    g_delta[(size_t)tok * D_INNER + col] = (acc > 20.f) ? acc : log1pf(__expf(acc));
}

// ---------------- 6. selective scan + D skip + silu(res) gate --------------
__global__ void scan_kernel(const float* __restrict__ A_log,
                            const float* __restrict__ Dp) {
    int lane = threadIdx.x & 15;                          // state index
    int ch = blockIdx.x * (blockDim.x >> 4) + (threadIdx.x >> 4);
    int b = ch >> 11;
    int d = ch & (D_INNER - 1);
    float a = -__expf(A_log[d * D_STATE + lane]);
    float Dv = Dp[d];
    float h = 0.f;
    size_t tok = (size_t)b * T_SZ;
    for (int t = 0; t < T_SZ; ++t, ++tok) {
        float dv = g_delta[tok * D_INNER + d];
        float uv = g_u[tok * D_INNER + d];
        float Bv = g_xdbc[tok * XDBC_W + DT_RANK + lane];
        float Cv = g_xdbc[tok * XDBC_W + DT_RANK + D_STATE + lane];
        float dA = __expf(dv * a);
        h = fmaf(dA, h, (dv * uv) * Bv);
        float p = h * Cv;
        p += __shfl_down_sync(0xffffffffu, p, 8, 16);
        p += __shfl_down_sync(0xffffffffu, p, 4, 16);
        p += __shfl_down_sync(0xffffffffu, p, 2, 16);
        p += __shfl_down_sync(0xffffffffu, p, 1, 16);
        if (lane == 0) {
            float res = g_xr[tok * (2 * D_INNER) + D_INNER + d];
            float sres = res / (1.f + __expf(-res));
            g_y[tok * D_INNER + d] = (p + uv * Dv) * sres;
        }
    }
}

// ---------------- launch ----------------------------------------------------
extern "C" void kernel_launch(void* const* d_in, const int* in_sizes, int n_in,
                              void* d_out, int out_size) {
    const float* x      = (const float*)d_in[0];
    const float* norm_w = (const float*)d_in[1];
    const float* w_in   = (const float*)d_in[2];
    const float* conv_w = (const float*)d_in[3];
    const float* conv_b = (const float*)d_in[4];
    const float* w_x    = (const float*)d_in[5];
    const float* w_dt   = (const float*)d_in[6];
    const float* b_dt   = (const float*)d_in[7];
    const float* A_log  = (const float*)d_in[8];
    const float* Dp     = (const float*)d_in[9];
    const float* w_out  = (const float*)d_in[10];
    float* out = (float*)d_out;

    void *p_xn = nullptr, *p_xr = nullptr, *p_y = nullptr;
    cudaGetSymbolAddress(&p_xn, g_xn);
    cudaGetSymbolAddress(&p_xr, g_xr);
    cudaGetSymbolAddress(&p_y, g_y);

    rmsnorm_kernel<<<NTOK, 256>>>(x, norm_w);

    gemm128<<<dim3(2 * D_INNER / BN, NTOK / BM), 256>>>(
        (const float*)p_xn, w_in, nullptr, (float*)p_xr, NTOK, 2 * D_INNER, D_MODEL);

    conv_silu_kernel<<<(NTOK * D_INNER + 255) / 256, 256>>>(conv_w, conv_b);

    proj_x_kernel<<<NTOK, 96>>>(w_x);

    delta_kernel<<<dim3(D_INNER / 256, NTOK), 256>>>(w_dt, b_dt);

    scan_kernel<<<(B_SZ * D_INNER) / 16, 256>>>(A_log, Dp);

    gemm128<<<dim3(D_MODEL / BN, NTOK / BM), 256>>>(
        (const float*)p_y, w_out, x, out, NTOK, D_MODEL, D_INNER);
}

// round 3
// speedup vs baseline: 1.0204x; 1.0204x over previous
#include <cuda_runtime.h>
#include <cuda_bf16.h>
#include <cstdint>

#define B_SZ 2
#define T_SZ 4096
#define D_MODEL 1024
#define D_STATE 16
#define D_CONV 4
#define D_INNER 2048
#define DT_RANK 64
#define NTOK (B_SZ * T_SZ)              // 8192
#define XDBC_W (DT_RANK + 2 * D_STATE)  // 96

// ---------------- scratch (device globals; no allocation allowed) ----------
__device__ float g_xn[NTOK * D_MODEL];
__device__ float g_xr[NTOK * 2 * D_INNER];
__device__ float g_u[NTOK * D_INNER];
__device__ float g_xdbc[NTOK * XDBC_W];
__device__ float g_delta[NTOK * D_INNER];
__device__ float g_y[NTOK * D_INNER];

// ---------------- 1. RMSNorm -----------------------------------------------
__global__ void rmsnorm_kernel(const float* __restrict__ x,
                               const float* __restrict__ w) {
    int tok = blockIdx.x;
    const float* xp = x + (size_t)tok * D_MODEL;
    float s = 0.f;
    for (int i = threadIdx.x; i < D_MODEL; i += 256) {
        float v = xp[i];
        s += v * v;
    }
    __shared__ float red[8];
    #pragma unroll
    for (int o = 16; o > 0; o >>= 1) s += __shfl_down_sync(0xffffffffu, s, o);
    if ((threadIdx.x & 31) == 0) red[threadIdx.x >> 5] = s;
    __syncthreads();
    if (threadIdx.x < 8) {
        float v = red[threadIdx.x];
        #pragma unroll
        for (int o = 4; o > 0; o >>= 1) v += __shfl_down_sync(0xffu, v, o, 8);
        if (threadIdx.x == 0) red[0] = rsqrtf(v / (float)D_MODEL + 1e-5f);
    }
    __syncthreads();
    float rs = red[0];
    float* op = g_xn + (size_t)tok * D_MODEL;
    for (int i = threadIdx.x; i < D_MODEL; i += 256) op[i] = xp[i] * rs * w[i];
}

// ---------------- 2. tf32 tensor-core GEMM ---------------------------------
// C[M,N] = A[M,K] @ W[K,N] (+resid). BM=BN=128, BK=32, 256 thr (8 warps 2x4),
// warp tile 64x32 = 4x4 m16n8k8 tiles.
#define AS_STRIDE 36    // conflict-free A-fragment LDS
#define BS_STRIDE 136   // conflict-free B-fragment LDS

__device__ __forceinline__ uint32_t f2tf32(float x) {
    uint32_t r;
    asm("cvt.rna.tf32.f32 %0, %1;" : "=r"(r) : "f"(x));
    return r;
}

template <bool NGUARD>
__global__ __launch_bounds__(256, 2)
void gemm_tf32(const float* __restrict__ A, const float* __restrict__ W,
               const float* __restrict__ resid, float* __restrict__ C,
               int M, int N, int K) {
    __shared__ float As[128][AS_STRIDE];
    __shared__ float Bs[32][BS_STRIDE];
    int tid = threadIdx.x;
    int lane = tid & 31, warp = tid >> 5;
    int wm = warp & 1, wn = warp >> 1;          // 2 x 4 warp grid
    int bm = blockIdx.y * 128, bn = blockIdx.x * 128;
    int t4 = lane >> 2, tm = lane & 3;
    float acc[4][4][4];
    #pragma unroll
    for (int i = 0; i < 4; i++)
        #pragma unroll
        for (int j = 0; j < 4; j++)
            #pragma unroll
            for (int r = 0; r < 4; r++) acc[i][j][r] = 0.f;

    int ar = tid >> 3, ac = (tid & 7) << 2;     // A: 32 rows/pass, 4 passes
    int br = tid >> 5, bc = (tid & 31) << 2;    // B: 8 rows/pass, 4 passes

    for (int k0 = 0; k0 < K; k0 += 32) {
        #pragma unroll
        for (int p = 0; p < 4; ++p) {
            int r = ar + p * 32;
            float4 v = *(const float4*)(A + (size_t)(bm + r) * K + k0 + ac);
            As[r][ac + 0] = __uint_as_float(f2tf32(v.x));
            As[r][ac + 1] = __uint_as_float(f2tf32(v.y));
            As[r][ac + 2] = __uint_as_float(f2tf32(v.z));
            As[r][ac + 3] = __uint_as_float(f2tf32(v.w));
        }
        #pragma unroll
        for (int p = 0; p < 4; ++p) {
            int r = br + p * 8;
            float4 v = make_float4(0.f, 0.f, 0.f, 0.f);
            if (!NGUARD || bn + bc < N)
                v = *(const float4*)(W + (size_t)(k0 + r) * N + bn + bc);
            Bs[r][bc + 0] = __uint_as_float(f2tf32(v.x));
            Bs[r][bc + 1] = __uint_as_float(f2tf32(v.y));
            Bs[r][bc + 2] = __uint_as_float(f2tf32(v.z));
            Bs[r][bc + 3] = __uint_as_float(f2tf32(v.w));
        }
        __syncthreads();

        #pragma unroll
        for (int ks = 0; ks < 4; ++ks) {
            int kb = ks * 8;
            uint32_t af[4][4], bf[4][2];
            #pragma unroll
            for (int im = 0; im < 4; im++) {
                int rb = wm * 64 + im * 16 + t4;
                af[im][0] = __float_as_uint(As[rb][kb + tm]);
                af[im][1] = __float_as_uint(As[rb + 8][kb + tm]);
                af[im][2] = __float_as_uint(As[rb][kb + tm + 4]);
                af[im][3] = __float_as_uint(As[rb + 8][kb + tm + 4]);
            }
            #pragma unroll
            for (int jn = 0; jn < 4; jn++) {
                int cb = wn * 32 + jn * 8 + t4;
                bf[jn][0] = __float_as_uint(Bs[kb + tm][cb]);
                bf[jn][1] = __float_as_uint(Bs[kb + tm + 4][cb]);
            }
            #pragma unroll
            for (int im = 0; im < 4; im++)
                #pragma unroll
                for (int jn = 0; jn < 4; jn++)
                    asm volatile(
                        "mma.sync.aligned.m16n8k8.row.col.f32.tf32.tf32.f32 "
                        "{%0,%1,%2,%3}, {%4,%5,%6,%7}, {%8,%9}, {%0,%1,%2,%3};\n"
                        : "+f"(acc[im][jn][0]), "+f"(acc[im][jn][1]),
                          "+f"(acc[im][jn][2]), "+f"(acc[im][jn][3])
                        : "r"(af[im][0]), "r"(af[im][1]),
                          "r"(af[im][2]), "r"(af[im][3]),
                          "r"(bf[jn][0]), "r"(bf[jn][1]));
        }
        __syncthreads();
    }

    #pragma unroll
    for (int im = 0; im < 4; im++) {
        int row = bm + wm * 64 + im * 16 + t4;
        #pragma unroll
        for (int jn = 0; jn < 4; jn++) {
            int col = bn + wn * 32 + jn * 8 + 2 * tm;
            if (NGUARD && col >= N) continue;
            size_t o0 = (size_t)row * N + col;
            size_t o1 = (size_t)(row + 8) * N + col;
            float2 v0 = make_float2(acc[im][jn][0], acc[im][jn][1]);
            float2 v1 = make_float2(acc[im][jn][2], acc[im][jn][3]);
            if (resid) {
                float2 r0 = *(const float2*)(resid + o0);
                float2 r1 = *(const float2*)(resid + o1);
                v0.x += r0.x; v0.y += r0.y;
                v1.x += r1.x; v1.y += r1.y;
            }
            *(float2*)(C + o0) = v0;
            *(float2*)(C + o1) = v1;
        }
    }
}

// ---------------- 3. depthwise causal conv (K=4) + bias + SiLU -------------
__global__ void conv_silu_kernel(const float* __restrict__ cw,
                                 const float* __restrict__ cb) {
    int idx = blockIdx.x * blockDim.x + threadIdx.x;
    if (idx >= NTOK * D_INNER) return;
    int d = idx & (D_INNER - 1);
    int tok = idx >> 11;
    int t = tok & (T_SZ - 1);
    float acc = cb[d];
    #pragma unroll
    for (int k = 0; k < D_CONV; ++k) {
        int tt = t - (D_CONV - 1) + k;
        if (tt >= 0)
            acc = fmaf(g_xr[(size_t)(tok - (D_CONV - 1) + k) * (2 * D_INNER) + d],
                       cw[d * D_CONV + k], acc);
    }
    g_u[idx] = acc / (1.f + __expf(-acc));
}

// ---------------- 5. delta = softplus(dt @ w_dt + b_dt) --------------------
__global__ void delta_kernel(const float* __restrict__ w_dt,
                             const float* __restrict__ b_dt) {
    __shared__ float dts[DT_RANK];
    int tok = blockIdx.y;
    int col = blockIdx.x * 256 + threadIdx.x;
    if (threadIdx.x < DT_RANK) dts[threadIdx.x] = g_xdbc[tok * XDBC_W + threadIdx.x];
    __syncthreads();
    float acc = b_dt[col];
    #pragma unroll 16
    for (int k = 0; k < DT_RANK; ++k)
        acc = fmaf(dts[k], w_dt[k * D_INNER + col], acc);
    g_delta[(size_t)tok * D_INNER + col] = (acc > 20.f) ? acc : log1pf(__expf(acc));
}

// ---------------- 6. selective scan + D skip + silu(res) gate --------------
__global__ void scan_kernel(const float* __restrict__ A_log,
                            const float* __restrict__ Dp) {
    int lane = threadIdx.x & 15;
    int ch = blockIdx.x * (blockDim.x >> 4) + (threadIdx.x >> 4);
    int b = ch >> 11;
    int d = ch & (D_INNER - 1);
    float a = -__expf(A_log[d * D_STATE + lane]);
    float Dv = Dp[d];
    float h = 0.f;
    size_t tok = (size_t)b * T_SZ;
    for (int t = 0; t < T_SZ; ++t, ++tok) {
        float dv = g_delta[tok * D_INNER + d];
        float uv = g_u[tok * D_INNER + d];
        float Bv = g_xdbc[tok * XDBC_W + DT_RANK + lane];
        float Cv = g_xdbc[tok * XDBC_W + DT_RANK + D_STATE + lane];
        float dA = __expf(dv * a);
        h = fmaf(dA, h, (dv * uv) * Bv);
        float p = h * Cv;
        p += __shfl_down_sync(0xffffffffu, p, 8, 16);
        p += __shfl_down_sync(0xffffffffu, p, 4, 16);
        p += __shfl_down_sync(0xffffffffu, p, 2, 16);
        p += __shfl_down_sync(0xffffffffu, p, 1, 16);
        if (lane == 0) {
            float res = g_xr[tok * (2 * D_INNER) + D_INNER + d];
            float sres = res / (1.f + __expf(-res));
            g_y[tok * D_INNER + d] = (p + uv * Dv) * sres;
        }
    }
}

// ---------------- launch ----------------------------------------------------
extern "C" void kernel_launch(void* const* d_in, const int* in_sizes, int n_in,
                              void* d_out, int out_size) {
    const float* x      = (const float*)d_in[0];
    const float* norm_w = (const float*)d_in[1];
    const float* w_in   = (const float*)d_in[2];
    const float* conv_w = (const float*)d_in[3];
    const float* conv_b = (const float*)d_in[4];
    const float* w_x    = (const float*)d_in[5];
    const float* w_dt   = (const float*)d_in[6];
    const float* b_dt   = (const float*)d_in[7];
    const float* A_log  = (const float*)d_in[8];
    const float* Dp     = (const float*)d_in[9];
    const float* w_out  = (const float*)d_in[10];
    float* out = (float*)d_out;

    void *p_xn = nullptr, *p_xr = nullptr, *p_u = nullptr, *p_xdbc = nullptr,
         *p_y = nullptr;
    cudaGetSymbolAddress(&p_xn, g_xn);
    cudaGetSymbolAddress(&p_xr, g_xr);
    cudaGetSymbolAddress(&p_u, g_u);
    cudaGetSymbolAddress(&p_xdbc, g_xdbc);
    cudaGetSymbolAddress(&p_y, g_y);

    rmsnorm_kernel<<<NTOK, 256>>>(x, norm_w);

    // xr = xn @ w_in  (8192 x 4096, K=1024)
    gemm_tf32<false><<<dim3(2 * D_INNER / 128, NTOK / 128), 256>>>(
        (const float*)p_xn, w_in, nullptr, (float*)p_xr, NTOK, 2 * D_INNER, D_MODEL);

    conv_silu_kernel<<<(NTOK * D_INNER + 255) / 256, 256>>>(conv_w, conv_b);

    // xdbc = u @ w_x  (8192 x 96, K=2048) — N-guarded GEMM
    gemm_tf32<true><<<dim3(1, NTOK / 128), 256>>>(
        (const float*)p_u, w_x, nullptr, (float*)p_xdbc, NTOK, XDBC_W, D_INNER);

    delta_kernel<<<dim3(D_INNER / 256, NTOK), 256>>>(w_dt, b_dt);

    scan_kernel<<<(B_SZ * D_INNER) / 16, 256>>>(A_log, Dp);

    // out = y @ w_out + x  (8192 x 1024, K=2048)
    gemm_tf32<false><<<dim3(D_MODEL / 128, NTOK / 128), 256>>>(
        (const float*)p_y, w_out, x, out, NTOK, D_MODEL, D_INNER);
}

// round 4
// speedup vs baseline: 3.7476x; 3.6728x over previous
#include <cuda_runtime.h>
#include <cuda_bf16.h>
#include <cstdint>

#define B_SZ 2
#define T_SZ 4096
#define D_MODEL 1024
#define D_STATE 16
#define D_CONV 4
#define D_INNER 2048
#define DT_RANK 64
#define NTOK (B_SZ * T_SZ)              // 8192
#define XDBC_W (DT_RANK + 2 * D_STATE)  // 96

// ---------------- scratch (device globals; no allocation allowed) ----------
__device__ float g_xn[NTOK * D_MODEL];
__device__ float g_xr[NTOK * 2 * D_INNER];
__device__ float g_u[NTOK * D_INNER];
__device__ float g_xdbc[NTOK * XDBC_W];
__device__ float g_delta[NTOK * D_INNER];
__device__ float g_y[NTOK * D_INNER];

// ---------------- cp.async helpers -----------------------------------------
__device__ __forceinline__ void cpa16(uint32_t dst, const void* src) {
    asm volatile("cp.async.cg.shared.global [%0], [%1], 16;\n" ::"r"(dst), "l"(src));
}
__device__ __forceinline__ void cpa_commit() {
    asm volatile("cp.async.commit_group;\n");
}
template <int N>
__device__ __forceinline__ void cpa_wait() {
    asm volatile("cp.async.wait_group %0;\n" ::"n"(N));
}

// ---------------- 1. RMSNorm -----------------------------------------------
__global__ void rmsnorm_kernel(const float* __restrict__ x,
                               const float* __restrict__ w) {
    int tok = blockIdx.x;
    const float* xp = x + (size_t)tok * D_MODEL;
    float s = 0.f;
    for (int i = threadIdx.x; i < D_MODEL; i += 256) {
        float v = xp[i];
        s += v * v;
    }
    __shared__ float red[8];
    #pragma unroll
    for (int o = 16; o > 0; o >>= 1) s += __shfl_down_sync(0xffffffffu, s, o);
    if ((threadIdx.x & 31) == 0) red[threadIdx.x >> 5] = s;
    __syncthreads();
    if (threadIdx.x < 8) {
        float v = red[threadIdx.x];
        #pragma unroll
        for (int o = 4; o > 0; o >>= 1) v += __shfl_down_sync(0xffu, v, o, 8);
        if (threadIdx.x == 0) red[0] = rsqrtf(v / (float)D_MODEL + 1e-5f);
    }
    __syncthreads();
    float rs = red[0];
    float* op = g_xn + (size_t)tok * D_MODEL;
    for (int i = threadIdx.x; i < D_MODEL; i += 256) op[i] = xp[i] * rs * w[i];
}

// ---------------- 2. tf32 tensor-core GEMM ---------------------------------
#define AS_STRIDE 36
#define BS_STRIDE 136

__device__ __forceinline__ uint32_t f2tf32(float x) {
    uint32_t r;
    asm("cvt.rna.tf32.f32 %0, %1;" : "=r"(r) : "f"(x));
    return r;
}

template <bool NGUARD>
__global__ __launch_bounds__(256, 2)
void gemm_tf32(const float* __restrict__ A, const float* __restrict__ W,
               const float* __restrict__ resid, float* __restrict__ C,
               int M, int N, int K) {
    __shared__ float As[128][AS_STRIDE];
    __shared__ float Bs[32][BS_STRIDE];
    int tid = threadIdx.x;
    int lane = tid & 31, warp = tid >> 5;
    int wm = warp & 1, wn = warp >> 1;
    int bm = blockIdx.y * 128, bn = blockIdx.x * 128;
    int t4 = lane >> 2, tm = lane & 3;
    float acc[4][4][4];
    #pragma unroll
    for (int i = 0; i < 4; i++)
        #pragma unroll
        for (int j = 0; j < 4; j++)
            #pragma unroll
            for (int r = 0; r < 4; r++) acc[i][j][r] = 0.f;

    int ar = tid >> 3, ac = (tid & 7) << 2;
    int br = tid >> 5, bc = (tid & 31) << 2;

    for (int k0 = 0; k0 < K; k0 += 32) {
        #pragma unroll
        for (int p = 0; p < 4; ++p) {
            int r = ar + p * 32;
            float4 v = *(const float4*)(A + (size_t)(bm + r) * K + k0 + ac);
            As[r][ac + 0] = __uint_as_float(f2tf32(v.x));
            As[r][ac + 1] = __uint_as_float(f2tf32(v.y));
            As[r][ac + 2] = __uint_as_float(f2tf32(v.z));
            As[r][ac + 3] = __uint_as_float(f2tf32(v.w));
        }
        #pragma unroll
        for (int p = 0; p < 4; ++p) {
            int r = br + p * 8;
            float4 v = make_float4(0.f, 0.f, 0.f, 0.f);
            if (!NGUARD || bn + bc < N)
                v = *(const float4*)(W + (size_t)(k0 + r) * N + bn + bc);
            Bs[r][bc + 0] = __uint_as_float(f2tf32(v.x));
            Bs[r][bc + 1] = __uint_as_float(f2tf32(v.y));
            Bs[r][bc + 2] = __uint_as_float(f2tf32(v.z));
            Bs[r][bc + 3] = __uint_as_float(f2tf32(v.w));
        }
        __syncthreads();

        #pragma unroll
        for (int ks = 0; ks < 4; ++ks) {
            int kb = ks * 8;
            uint32_t af[4][4], bf[4][2];
            #pragma unroll
            for (int im = 0; im < 4; im++) {
                int rb = wm * 64 + im * 16 + t4;
                af[im][0] = __float_as_uint(As[rb][kb + tm]);
                af[im][1] = __float_as_uint(As[rb + 8][kb + tm]);
                af[im][2] = __float_as_uint(As[rb][kb + tm + 4]);
                af[im][3] = __float_as_uint(As[rb + 8][kb + tm + 4]);
            }
            #pragma unroll
            for (int jn = 0; jn < 4; jn++) {
                int cb = wn * 32 + jn * 8 + t4;
                bf[jn][0] = __float_as_uint(Bs[kb + tm][cb]);
                bf[jn][1] = __float_as_uint(Bs[kb + tm + 4][cb]);
            }
            #pragma unroll
            for (int im = 0; im < 4; im++)
                #pragma unroll
                for (int jn = 0; jn < 4; jn++)
                    asm volatile(
                        "mma.sync.aligned.m16n8k8.row.col.f32.tf32.tf32.f32 "
                        "{%0,%1,%2,%3}, {%4,%5,%6,%7}, {%8,%9}, {%0,%1,%2,%3};\n"
                        : "+f"(acc[im][jn][0]), "+f"(acc[im][jn][1]),
                          "+f"(acc[im][jn][2]), "+f"(acc[im][jn][3])
                        : "r"(af[im][0]), "r"(af[im][1]),
                          "r"(af[im][2]), "r"(af[im][3]),
                          "r"(bf[jn][0]), "r"(bf[jn][1]));
        }
        __syncthreads();
    }

    #pragma unroll
    for (int im = 0; im < 4; im++) {
        int row = bm + wm * 64 + im * 16 + t4;
        #pragma unroll
        for (int jn = 0; jn < 4; jn++) {
            int col = bn + wn * 32 + jn * 8 + 2 * tm;
            if (NGUARD && col >= N) continue;
            size_t o0 = (size_t)row * N + col;
            size_t o1 = (size_t)(row + 8) * N + col;
            float2 v0 = make_float2(acc[im][jn][0], acc[im][jn][1]);
            float2 v1 = make_float2(acc[im][jn][2], acc[im][jn][3]);
            if (resid) {
                float2 r0 = *(const float2*)(resid + o0);
                float2 r1 = *(const float2*)(resid + o1);
                v0.x += r0.x; v0.y += r0.y;
                v1.x += r1.x; v1.y += r1.y;
            }
            *(float2*)(C + o0) = v0;
            *(float2*)(C + o1) = v1;
        }
    }
}

// ---------------- 3. depthwise causal conv (K=4) + bias + SiLU -------------
__global__ void conv_silu_kernel(const float* __restrict__ cw,
                                 const float* __restrict__ cb) {
    int idx = blockIdx.x * blockDim.x + threadIdx.x;
    if (idx >= NTOK * D_INNER) return;
    int d = idx & (D_INNER - 1);
    int tok = idx >> 11;
    int t = tok & (T_SZ - 1);
    float acc = cb[d];
    #pragma unroll
    for (int k = 0; k < D_CONV; ++k) {
        int tt = t - (D_CONV - 1) + k;
        if (tt >= 0)
            acc = fmaf(g_xr[(size_t)(tok - (D_CONV - 1) + k) * (2 * D_INNER) + d],
                       cw[d * D_CONV + k], acc);
    }
    g_u[idx] = acc / (1.f + __expf(-acc));
}

// ---------------- 5. delta = softplus(dt @ w_dt + b_dt) --------------------
__global__ void delta_kernel(const float* __restrict__ w_dt,
                             const float* __restrict__ b_dt) {
    __shared__ float dts[DT_RANK];
    int tok = blockIdx.y;
    int col = blockIdx.x * 256 + threadIdx.x;
    if (threadIdx.x < DT_RANK) dts[threadIdx.x] = g_xdbc[tok * XDBC_W + threadIdx.x];
    __syncthreads();
    float acc = b_dt[col];
    #pragma unroll 16
    for (int k = 0; k < DT_RANK; ++k)
        acc = fmaf(dts[k], w_dt[k * D_INNER + col], acc);
    g_delta[(size_t)tok * D_INNER + col] = (acc > 20.f) ? acc : log1pf(__expf(acc));
}

// ---------------- 6. smem-staged selective scan -----------------------------
// 128 blocks x 512 threads. Block owns 32 channels (of B*D_INNER=4096) for the
// full T=4096 sequence, processed in TC=32 chunks double-buffered via cp.async.
#define SCAN_TC 32
#define SCAN_CH 32
#define SCAN_NC (T_SZ / SCAN_TC)

__global__ __launch_bounds__(512, 1)
void scan_kernel(const float* __restrict__ A_log, const float* __restrict__ Dp) {
    __shared__ float sD[2][SCAN_TC][SCAN_CH];
    __shared__ float sU[2][SCAN_TC][SCAN_CH];
    __shared__ float sR[2][SCAN_TC][SCAN_CH];
    __shared__ float sBC[2][SCAN_TC][32];        // [B(16) | C(16)] per token
    __shared__ float sY[SCAN_TC][SCAN_CH];

    int tid = threadIdx.x;
    int bb = blockIdx.x >> 6;                    // batch
    int d0 = (blockIdx.x & 63) * SCAN_CH;        // channel base within D_INNER
    size_t tokbase = (size_t)bb * T_SZ;

    // loader mapping: tid 0..255 -> delta+u ; tid 256..511 -> res+bc
    int lidx = tid & 255;
    int li = lidx >> 3;                          // row 0..31
    int lj = (lidx & 7) << 2;                    // col 0..28 step 4
    int lgrp = tid >> 8;

    // compute mapping
    int warp = tid >> 5, lane = tid & 31;
    int ch = warp * 2 + (lane >> 4);             // 0..31
    int n = lane & 15;                           // state index
    int dg = d0 + ch;
    float a = -__expf(A_log[dg * D_STATE + n]);
    float Dv = Dp[dg];
    float h = 0.f;

    auto issue_chunk = [&](int c, int buf) {
        size_t tok = tokbase + (size_t)c * SCAN_TC + li;
        if (lgrp == 0) {
            cpa16((uint32_t)__cvta_generic_to_shared(&sD[buf][li][lj]),
                  g_delta + tok * D_INNER + d0 + lj);
            cpa16((uint32_t)__cvta_generic_to_shared(&sU[buf][li][lj]),
                  g_u + tok * D_INNER + d0 + lj);
        } else {
            cpa16((uint32_t)__cvta_generic_to_shared(&sR[buf][li][lj]),
                  g_xr + tok * (2 * D_INNER) + D_INNER + d0 + lj);
            cpa16((uint32_t)__cvta_generic_to_shared(&sBC[buf][li][lj]),
                  g_xdbc + tok * XDBC_W + DT_RANK + lj);
        }
        cpa_commit();
    };

    issue_chunk(0, 0);

    for (int c = 0; c < SCAN_NC; ++c) {
        int buf = c & 1;
        if (c + 1 < SCAN_NC) {
            issue_chunk(c + 1, buf ^ 1);
            cpa_wait<1>();
        } else {
            cpa_wait<0>();
        }
        __syncthreads();   // chunk c visible to all; also protects sY reuse

        #pragma unroll 4
        for (int t = 0; t < SCAN_TC; ++t) {
            float dv = sD[buf][t][ch];
            float uv = sU[buf][t][ch];
            float Bv = sBC[buf][t][n];
            float Cv = sBC[buf][t][16 + n];
            h = fmaf(__expf(dv * a), h, (dv * uv) * Bv);
            float p = h * Cv;
            p += __shfl_down_sync(0xffffffffu, p, 8, 16);
            p += __shfl_down_sync(0xffffffffu, p, 4, 16);
            p += __shfl_down_sync(0xffffffffu, p, 2, 16);
            p += __shfl_down_sync(0xffffffffu, p, 1, 16);
            if (n == 0) {
                float res = sR[buf][t][ch];
                float sres = res / (1.f + __expf(-res));
                sY[t][ch] = fmaf(uv, Dv, p) * sres;
            }
        }
        __syncthreads();   // sY complete

        // coalesced y store (half the threads)
        if (lgrp == 0) {
            size_t tok = tokbase + (size_t)c * SCAN_TC + li;
            *(float4*)(g_y + tok * D_INNER + d0 + lj) = *(float4*)(&sY[li][lj]);
        }
    }
}

// ---------------- launch ----------------------------------------------------
extern "C" void kernel_launch(void* const* d_in, const int* in_sizes, int n_in,
                              void* d_out, int out_size) {
    const float* x      = (const float*)d_in[0];
    const float* norm_w = (const float*)d_in[1];
    const float* w_in   = (const float*)d_in[2];
    const float* conv_w = (const float*)d_in[3];
    const float* conv_b = (const float*)d_in[4];
    const float* w_x    = (const float*)d_in[5];
    const float* w_dt   = (const float*)d_in[6];
    const float* b_dt   = (const float*)d_in[7];
    const float* A_log  = (const float*)d_in[8];
    const float* Dp     = (const float*)d_in[9];
    const float* w_out  = (const float*)d_in[10];
    float* out = (float*)d_out;

    void *p_xn = nullptr, *p_xr = nullptr, *p_u = nullptr, *p_xdbc = nullptr,
         *p_y = nullptr;
    cudaGetSymbolAddress(&p_xn, g_xn);
    cudaGetSymbolAddress(&p_xr, g_xr);
    cudaGetSymbolAddress(&p_u, g_u);
    cudaGetSymbolAddress(&p_xdbc, g_xdbc);
    cudaGetSymbolAddress(&p_y, g_y);

    rmsnorm_kernel<<<NTOK, 256>>>(x, norm_w);

    // xr = xn @ w_in  (8192 x 4096, K=1024)
    gemm_tf32<false><<<dim3(2 * D_INNER / 128, NTOK / 128), 256>>>(
        (const float*)p_xn, w_in, nullptr, (float*)p_xr, NTOK, 2 * D_INNER, D_MODEL);

    conv_silu_kernel<<<(NTOK * D_INNER + 255) / 256, 256>>>(conv_w, conv_b);

    // xdbc = u @ w_x  (8192 x 96, K=2048)
    gemm_tf32<true><<<dim3(1, NTOK / 128), 256>>>(
        (const float*)p_u, w_x, nullptr, (float*)p_xdbc, NTOK, XDBC_W, D_INNER);

    delta_kernel<<<dim3(D_INNER / 256, NTOK), 256>>>(w_dt, b_dt);

    scan_kernel<<<B_SZ * D_INNER / SCAN_CH, 512>>>(A_log, Dp);

    // out = y @ w_out + x  (8192 x 1024, K=2048)
    gemm_tf32<false><<<dim3(D_MODEL / 128, NTOK / 128), 256>>>(
        (const float*)p_y, w_out, x, out, NTOK, D_MODEL, D_INNER);
}

// round 5
// speedup vs baseline: 4.1927x; 1.1188x over previous
#include <cuda_runtime.h>
#include <cuda_bf16.h>
#include <cstdint>

#define B_SZ 2
#define T_SZ 4096
#define D_MODEL 1024
#define D_STATE 16
#define D_CONV 4
#define D_INNER 2048
#define DT_RANK 64
#define NTOK (B_SZ * T_SZ)              // 8192
#define XDBC_W (DT_RANK + 2 * D_STATE)  // 96

// ---------------- scratch (device globals; no allocation allowed) ----------
__device__ float g_xn[NTOK * D_MODEL];
__device__ float g_xr[NTOK * 2 * D_INNER];
__device__ float g_u[NTOK * D_INNER];
__device__ float g_xdbc[NTOK * XDBC_W];
__device__ float g_delta[NTOK * D_INNER];
__device__ float g_y[NTOK * D_INNER];

// ---------------- cp.async helpers -----------------------------------------
__device__ __forceinline__ void cpa16(uint32_t dst, const void* src) {
    asm volatile("cp.async.cg.shared.global [%0], [%1], 16;\n" ::"r"(dst), "l"(src));
}
__device__ __forceinline__ void cpa16_guard(uint32_t dst, const void* src, int sz) {
    asm volatile("cp.async.cg.shared.global [%0], [%1], 16, %2;\n"
                 ::"r"(dst), "l"(src), "r"(sz));
}
__device__ __forceinline__ void cpa_commit() {
    asm volatile("cp.async.commit_group;\n");
}
template <int N>
__device__ __forceinline__ void cpa_wait() {
    asm volatile("cp.async.wait_group %0;\n" ::"n"(N));
}

// ---------------- 1. RMSNorm -----------------------------------------------
__global__ void rmsnorm_kernel(const float* __restrict__ x,
                               const float* __restrict__ w) {
    int tok = blockIdx.x;
    const float* xp = x + (size_t)tok * D_MODEL;
    float s = 0.f;
    for (int i = threadIdx.x; i < D_MODEL; i += 256) {
        float v = xp[i];
        s += v * v;
    }
    __shared__ float red[8];
    #pragma unroll
    for (int o = 16; o > 0; o >>= 1) s += __shfl_down_sync(0xffffffffu, s, o);
    if ((threadIdx.x & 31) == 0) red[threadIdx.x >> 5] = s;
    __syncthreads();
    if (threadIdx.x < 8) {
        float v = red[threadIdx.x];
        #pragma unroll
        for (int o = 4; o > 0; o >>= 1) v += __shfl_down_sync(0xffu, v, o, 8);
        if (threadIdx.x == 0) red[0] = rsqrtf(v / (float)D_MODEL + 1e-5f);
    }
    __syncthreads();
    float rs = red[0];
    float* op = g_xn + (size_t)tok * D_MODEL;
    for (int i = threadIdx.x; i < D_MODEL; i += 256) op[i] = xp[i] * rs * w[i];
}

// ---------------- 2. pipelined tf32 tensor-core GEMM ------------------------
// C[M,N] = A[M,K] @ W[K,N] (+resid). BM=BN=128, BK=32, double-buffered
// cp.async. 256 thr (8 warps 2x4), warp tile 64x32 = 4x4 m16n8k8.
// Raw fp32 fed to tf32 mma (HW truncation) — no cvt on the load path.
#define AS_STRIDE 36
#define BS_STRIDE 136
#define A_STAGE_F (128 * AS_STRIDE)               // 4608 floats
#define B_STAGE_F (32 * BS_STRIDE)                // 4352 floats
#define STAGE_F (A_STAGE_F + B_STAGE_F)           // 8960 floats
#define GEMM_SMEM_BYTES (2 * STAGE_F * 4)         // 71680 B

template <bool NGUARD>
__global__ __launch_bounds__(256, 2)
void gemm_tf32(const float* __restrict__ A, const float* __restrict__ W,
               const float* __restrict__ resid, float* __restrict__ C,
               int M, int N, int K) {
    extern __shared__ float smem[];
    int tid = threadIdx.x;
    int lane = tid & 31, warp = tid >> 5;
    int wm = warp & 1, wn = warp >> 1;
    int bm = blockIdx.y * 128, bn = blockIdx.x * 128;
    int t4 = lane >> 2, tm = lane & 3;
    float acc[4][4][4];
    #pragma unroll
    for (int i = 0; i < 4; i++)
        #pragma unroll
        for (int j = 0; j < 4; j++)
            #pragma unroll
            for (int r = 0; r < 4; r++) acc[i][j][r] = 0.f;

    int ar = tid >> 3, ac = (tid & 7) << 2;   // A: rows ar+32p, col ac
    int br = tid >> 5, bc = (tid & 31) << 2;  // B: rows br+8p,  col bc

    int nt = K >> 5;   // number of BK=32 tiles

    auto issue = [&](int c, int buf) {
        float* pA = smem + buf * STAGE_F;
        float* pB = pA + A_STAGE_F;
        int k0 = c << 5;
        #pragma unroll
        for (int p = 0; p < 4; ++p) {
            int r = ar + p * 32;
            cpa16((uint32_t)__cvta_generic_to_shared(pA + r * AS_STRIDE + ac),
                  A + (size_t)(bm + r) * K + k0 + ac);
        }
        #pragma unroll
        for (int p = 0; p < 4; ++p) {
            int r = br + p * 8;
            const float* src = W + (size_t)(k0 + r) * N + bn + bc;
            uint32_t dst = (uint32_t)__cvta_generic_to_shared(pB + r * BS_STRIDE + bc);
            if (NGUARD)
                cpa16_guard(dst, src, (bn + bc < N) ? 16 : 0);
            else
                cpa16(dst, src);
        }
        cpa_commit();
    };

    issue(0, 0);

    for (int c = 0; c < nt; ++c) {
        int buf = c & 1;
        if (c + 1 < nt) {
            issue(c + 1, buf ^ 1);
            cpa_wait<1>();
        } else {
            cpa_wait<0>();
        }
        __syncthreads();

        float* pA = smem + buf * STAGE_F;
        float* pB = pA + A_STAGE_F;
        #pragma unroll
        for (int ks = 0; ks < 4; ++ks) {
            int kb = ks * 8;
            uint32_t af[4][4], bf[4][2];
            #pragma unroll
            for (int im = 0; im < 4; im++) {
                int rb = wm * 64 + im * 16 + t4;
                af[im][0] = __float_as_uint(pA[rb * AS_STRIDE + kb + tm]);
                af[im][1] = __float_as_uint(pA[(rb + 8) * AS_STRIDE + kb + tm]);
                af[im][2] = __float_as_uint(pA[rb * AS_STRIDE + kb + tm + 4]);
                af[im][3] = __float_as_uint(pA[(rb + 8) * AS_STRIDE + kb + tm + 4]);
            }
            #pragma unroll
            for (int jn = 0; jn < 4; jn++) {
                int cb = wn * 32 + jn * 8 + t4;
                bf[jn][0] = __float_as_uint(pB[(kb + tm) * BS_STRIDE + cb]);
                bf[jn][1] = __float_as_uint(pB[(kb + tm + 4) * BS_STRIDE + cb]);
            }
            #pragma unroll
            for (int im = 0; im < 4; im++)
                #pragma unroll
                for (int jn = 0; jn < 4; jn++)
                    asm volatile(
                        "mma.sync.aligned.m16n8k8.row.col.f32.tf32.tf32.f32 "
                        "{%0,%1,%2,%3}, {%4,%5,%6,%7}, {%8,%9}, {%0,%1,%2,%3};\n"
                        : "+f"(acc[im][jn][0]), "+f"(acc[im][jn][1]),
                          "+f"(acc[im][jn][2]), "+f"(acc[im][jn][3])
                        : "r"(af[im][0]), "r"(af[im][1]),
                          "r"(af[im][2]), "r"(af[im][3]),
                          "r"(bf[jn][0]), "r"(bf[jn][1]));
        }
        __syncthreads();
    }

    #pragma unroll
    for (int im = 0; im < 4; im++) {
        int row = bm + wm * 64 + im * 16 + t4;
        #pragma unroll
        for (int jn = 0; jn < 4; jn++) {
            int col = bn + wn * 32 + jn * 8 + 2 * tm;
            if (NGUARD && col >= N) continue;
            size_t o0 = (size_t)row * N + col;
            size_t o1 = (size_t)(row + 8) * N + col;
            float2 v0 = make_float2(acc[im][jn][0], acc[im][jn][1]);
            float2 v1 = make_float2(acc[im][jn][2], acc[im][jn][3]);
            if (resid) {
                float2 r0 = *(const float2*)(resid + o0);
                float2 r1 = *(const float2*)(resid + o1);
                v0.x += r0.x; v0.y += r0.y;
                v1.x += r1.x; v1.y += r1.y;
            }
            *(float2*)(C + o0) = v0;
            *(float2*)(C + o1) = v1;
        }
    }
}

// ---------------- 3. depthwise causal conv (K=4) + bias + SiLU -------------
__global__ void conv_silu_kernel(const float* __restrict__ cw,
                                 const float* __restrict__ cb) {
    int idx = blockIdx.x * blockDim.x + threadIdx.x;
    if (idx >= NTOK * D_INNER) return;
    int d = idx & (D_INNER - 1);
    int tok = idx >> 11;
    int t = tok & (T_SZ - 1);
    float acc = cb[d];
    #pragma unroll
    for (int k = 0; k < D_CONV; ++k) {
        int tt = t - (D_CONV - 1) + k;
        if (tt >= 0)
            acc = fmaf(g_xr[(size_t)(tok - (D_CONV - 1) + k) * (2 * D_INNER) + d],
                       cw[d * D_CONV + k], acc);
    }
    g_u[idx] = acc / (1.f + __expf(-acc));
}

// ---------------- 5. delta = softplus(dt @ w_dt + b_dt) --------------------
__global__ void delta_kernel(const float* __restrict__ w_dt,
                             const float* __restrict__ b_dt) {
    __shared__ float dts[DT_RANK];
    int tok = blockIdx.y;
    int col = blockIdx.x * 256 + threadIdx.x;
    if (threadIdx.x < DT_RANK) dts[threadIdx.x] = g_xdbc[tok * XDBC_W + threadIdx.x];
    __syncthreads();
    float acc = b_dt[col];
    #pragma unroll 16
    for (int k = 0; k < DT_RANK; ++k)
        acc = fmaf(dts[k], w_dt[k * D_INNER + col], acc);
    g_delta[(size_t)tok * D_INNER + col] = (acc > 20.f) ? acc : log1pf(__expf(acc));
}

// ---------------- 6. smem-staged selective scan -----------------------------
#define SCAN_TC 32
#define SCAN_CH 32
#define SCAN_NC (T_SZ / SCAN_TC)

__global__ __launch_bounds__(512, 1)
void scan_kernel(const float* __restrict__ A_log, const float* __restrict__ Dp) {
    __shared__ float sD[2][SCAN_TC][SCAN_CH];
    __shared__ float sU[2][SCAN_TC][SCAN_CH];
    __shared__ float sR[2][SCAN_TC][SCAN_CH];
    __shared__ float sBC[2][SCAN_TC][32];
    __shared__ float sY[SCAN_TC][SCAN_CH];

    int tid = threadIdx.x;
    int bb = blockIdx.x >> 6;
    int d0 = (blockIdx.x & 63) * SCAN_CH;
    size_t tokbase = (size_t)bb * T_SZ;

    int lidx = tid & 255;
    int li = lidx >> 3;
    int lj = (lidx & 7) << 2;
    int lgrp = tid >> 8;

    int warp = tid >> 5, lane = tid & 31;
    int ch = warp * 2 + (lane >> 4);
    int n = lane & 15;
    int dg = d0 + ch;
    float a = -__expf(A_log[dg * D_STATE + n]);
    float Dv = Dp[dg];
    float h = 0.f;

    auto issue_chunk = [&](int c, int buf) {
        size_t tok = tokbase + (size_t)c * SCAN_TC + li;
        if (lgrp == 0) {
            cpa16((uint32_t)__cvta_generic_to_shared(&sD[buf][li][lj]),
                  g_delta + tok * D_INNER + d0 + lj);
            cpa16((uint32_t)__cvta_generic_to_shared(&sU[buf][li][lj]),
                  g_u + tok * D_INNER + d0 + lj);
        } else {
            cpa16((uint32_t)__cvta_generic_to_shared(&sR[buf][li][lj]),
                  g_xr + tok * (2 * D_INNER) + D_INNER + d0 + lj);
            cpa16((uint32_t)__cvta_generic_to_shared(&sBC[buf][li][lj]),
                  g_xdbc + tok * XDBC_W + DT_RANK + lj);
        }
        cpa_commit();
    };

    issue_chunk(0, 0);

    for (int c = 0; c < SCAN_NC; ++c) {
        int buf = c & 1;
        if (c + 1 < SCAN_NC) {
            issue_chunk(c + 1, buf ^ 1);
            cpa_wait<1>();
        } else {
            cpa_wait<0>();
        }
        __syncthreads();

        #pragma unroll 4
        for (int t = 0; t < SCAN_TC; ++t) {
            float dv = sD[buf][t][ch];
            float uv = sU[buf][t][ch];
            float Bv = sBC[buf][t][n];
            float Cv = sBC[buf][t][16 + n];
            h = fmaf(__expf(dv * a), h, (dv * uv) * Bv);
            float p = h * Cv;
            p += __shfl_down_sync(0xffffffffu, p, 8, 16);
            p += __shfl_down_sync(0xffffffffu, p, 4, 16);
            p += __shfl_down_sync(0xffffffffu, p, 2, 16);
            p += __shfl_down_sync(0xffffffffu, p, 1, 16);
            if (n == 0) {
                float res = sR[buf][t][ch];
                float sres = res / (1.f + __expf(-res));
                sY[t][ch] = fmaf(uv, Dv, p) * sres;
            }
        }
        __syncthreads();

        if (lgrp == 0) {
            size_t tok = tokbase + (size_t)c * SCAN_TC + li;
            *(float4*)(g_y + tok * D_INNER + d0 + lj) = *(float4*)(&sY[li][lj]);
        }
    }
}

// ---------------- launch ----------------------------------------------------
extern "C" void kernel_launch(void* const* d_in, const int* in_sizes, int n_in,
                              void* d_out, int out_size) {
    const float* x      = (const float*)d_in[0];
    const float* norm_w = (const float*)d_in[1];
    const float* w_in   = (const float*)d_in[2];
    const float* conv_w = (const float*)d_in[3];
    const float* conv_b = (const float*)d_in[4];
    const float* w_x    = (const float*)d_in[5];
    const float* w_dt   = (const float*)d_in[6];
    const float* b_dt   = (const float*)d_in[7];
    const float* A_log  = (const float*)d_in[8];
    const float* Dp     = (const float*)d_in[9];
    const float* w_out  = (const float*)d_in[10];
    float* out = (float*)d_out;

    void *p_xn = nullptr, *p_xr = nullptr, *p_u = nullptr, *p_xdbc = nullptr,
         *p_y = nullptr;
    cudaGetSymbolAddress(&p_xn, g_xn);
    cudaGetSymbolAddress(&p_xr, g_xr);
    cudaGetSymbolAddress(&p_u, g_u);
    cudaGetSymbolAddress(&p_xdbc, g_xdbc);
    cudaGetSymbolAddress(&p_y, g_y);

    cudaFuncSetAttribute(gemm_tf32<false>,
                         cudaFuncAttributeMaxDynamicSharedMemorySize, GEMM_SMEM_BYTES);
    cudaFuncSetAttribute(gemm_tf32<true>,
                         cudaFuncAttributeMaxDynamicSharedMemorySize, GEMM_SMEM_BYTES);

    rmsnorm_kernel<<<NTOK, 256>>>(x, norm_w);

    // xr = xn @ w_in  (8192 x 4096, K=1024)
    gemm_tf32<false><<<dim3(2 * D_INNER / 128, NTOK / 128), 256, GEMM_SMEM_BYTES>>>(
        (const float*)p_xn, w_in, nullptr, (float*)p_xr, NTOK, 2 * D_INNER, D_MODEL);

    conv_silu_kernel<<<(NTOK * D_INNER + 255) / 256, 256>>>(conv_w, conv_b);

    // xdbc = u @ w_x  (8192 x 96, K=2048)
    gemm_tf32<true><<<dim3(1, NTOK / 128), 256, GEMM_SMEM_BYTES>>>(
        (const float*)p_u, w_x, nullptr, (float*)p_xdbc, NTOK, XDBC_W, D_INNER);

    delta_kernel<<<dim3(D_INNER / 256, NTOK), 256>>>(w_dt, b_dt);

    scan_kernel<<<B_SZ * D_INNER / SCAN_CH, 512>>>(A_log, Dp);

    // out = y @ w_out + x  (8192 x 1024, K=2048)
    gemm_tf32<false><<<dim3(D_MODEL / 128, NTOK / 128), 256, GEMM_SMEM_BYTES>>>(
        (const float*)p_y, w_out, x, out, NTOK, D_MODEL, D_INNER);
}

// round 6
// speedup vs baseline: 5.7689x; 1.3759x over previous
#include <cuda_runtime.h>
#include <cuda_bf16.h>
#include <cstdint>

#define B_SZ 2
#define T_SZ 4096
#define D_MODEL 1024
#define D_STATE 16
#define D_CONV 4
#define D_INNER 2048
#define DT_RANK 64
#define NTOK (B_SZ * T_SZ)              // 8192
#define XDBC_W (DT_RANK + 2 * D_STATE)  // 96

// ---------------- scratch (device globals; no allocation allowed) ----------
__device__ float g_xn[NTOK * D_MODEL];
__device__ float g_xr[NTOK * 2 * D_INNER];   // [u | silu(res)] after epilogue
__device__ float g_u[NTOK * D_INNER];
__device__ float g_xdbc[NTOK * XDBC_W];
__device__ float g_delta[NTOK * D_INNER];
__device__ float g_y[NTOK * D_INNER];

// ---------------- cp.async helpers -----------------------------------------
__device__ __forceinline__ void cpa16(uint32_t dst, const void* src) {
    asm volatile("cp.async.cg.shared.global [%0], [%1], 16;\n" ::"r"(dst), "l"(src));
}
__device__ __forceinline__ void cpa16_guard(uint32_t dst, const void* src, int sz) {
    asm volatile("cp.async.cg.shared.global [%0], [%1], 16, %2;\n"
                 ::"r"(dst), "l"(src), "r"(sz));
}
__device__ __forceinline__ void cpa_commit() {
    asm volatile("cp.async.commit_group;\n");
}
template <int N>
__device__ __forceinline__ void cpa_wait() {
    asm volatile("cp.async.wait_group %0;\n" ::"n"(N));
}

// ---------------- 1. RMSNorm -----------------------------------------------
__global__ void rmsnorm_kernel(const float* __restrict__ x,
                               const float* __restrict__ w) {
    int tok = blockIdx.x;
    const float* xp = x + (size_t)tok * D_MODEL;
    float s = 0.f;
    for (int i = threadIdx.x; i < D_MODEL; i += 256) {
        float v = xp[i];
        s += v * v;
    }
    __shared__ float red[8];
    #pragma unroll
    for (int o = 16; o > 0; o >>= 1) s += __shfl_down_sync(0xffffffffu, s, o);
    if ((threadIdx.x & 31) == 0) red[threadIdx.x >> 5] = s;
    __syncthreads();
    if (threadIdx.x < 8) {
        float v = red[threadIdx.x];
        #pragma unroll
        for (int o = 4; o > 0; o >>= 1) v += __shfl_down_sync(0xffu, v, o, 8);
        if (threadIdx.x == 0) red[0] = rsqrtf(v / (float)D_MODEL + 1e-5f);
    }
    __syncthreads();
    float rs = red[0];
    float* op = g_xn + (size_t)tok * D_MODEL;
    for (int i = threadIdx.x; i < D_MODEL; i += 256) op[i] = xp[i] * rs * w[i];
}

// ---------------- 2. pipelined tf32 tensor-core GEMM ------------------------
// C[M,N] = epi(A[M,K](lda) @ W[K,N]) (+resid). BM=BN=128, BK=32,
// double-buffered cp.async. EPI: 0 none, 1 silu for col>=N/2, 2 softplus+bias.
#define AS_STRIDE 36
#define BS_STRIDE 136
#define A_STAGE_F (128 * AS_STRIDE)
#define B_STAGE_F (32 * BS_STRIDE)
#define STAGE_F (A_STAGE_F + B_STAGE_F)
#define GEMM_SMEM_BYTES (2 * STAGE_F * 4)         // 71680 B

template <bool NGUARD, int EPI>
__global__ __launch_bounds__(256, 2)
void gemm_tf32(const float* __restrict__ A, const float* __restrict__ W,
               const float* __restrict__ resid, const float* __restrict__ bias,
               float* __restrict__ C, int M, int N, int K, int lda) {
    extern __shared__ float smem[];
    int tid = threadIdx.x;
    int lane = tid & 31, warp = tid >> 5;
    int wm = warp & 1, wn = warp >> 1;
    int bm = blockIdx.y * 128, bn = blockIdx.x * 128;
    int t4 = lane >> 2, tm = lane & 3;
    float acc[4][4][4];
    #pragma unroll
    for (int i = 0; i < 4; i++)
        #pragma unroll
        for (int j = 0; j < 4; j++)
            #pragma unroll
            for (int r = 0; r < 4; r++) acc[i][j][r] = 0.f;

    int ar = tid >> 3, ac = (tid & 7) << 2;
    int br = tid >> 5, bc = (tid & 31) << 2;

    int nt = K >> 5;

    auto issue = [&](int c, int buf) {
        float* pA = smem + buf * STAGE_F;
        float* pB = pA + A_STAGE_F;
        int k0 = c << 5;
        #pragma unroll
        for (int p = 0; p < 4; ++p) {
            int r = ar + p * 32;
            cpa16((uint32_t)__cvta_generic_to_shared(pA + r * AS_STRIDE + ac),
                  A + (size_t)(bm + r) * lda + k0 + ac);
        }
        #pragma unroll
        for (int p = 0; p < 4; ++p) {
            int r = br + p * 8;
            const float* src = W + (size_t)(k0 + r) * N + bn + bc;
            uint32_t dst = (uint32_t)__cvta_generic_to_shared(pB + r * BS_STRIDE + bc);
            if (NGUARD)
                cpa16_guard(dst, src, (bn + bc < N) ? 16 : 0);
            else
                cpa16(dst, src);
        }
        cpa_commit();
    };

    issue(0, 0);

    for (int c = 0; c < nt; ++c) {
        int buf = c & 1;
        if (c + 1 < nt) {
            issue(c + 1, buf ^ 1);
            cpa_wait<1>();
        } else {
            cpa_wait<0>();
        }
        __syncthreads();

        float* pA = smem + buf * STAGE_F;
        float* pB = pA + A_STAGE_F;
        #pragma unroll
        for (int ks = 0; ks < 4; ++ks) {
            int kb = ks * 8;
            uint32_t af[4][4], bf[4][2];
            #pragma unroll
            for (int im = 0; im < 4; im++) {
                int rb = wm * 64 + im * 16 + t4;
                af[im][0] = __float_as_uint(pA[rb * AS_STRIDE + kb + tm]);
                af[im][1] = __float_as_uint(pA[(rb + 8) * AS_STRIDE + kb + tm]);
                af[im][2] = __float_as_uint(pA[rb * AS_STRIDE + kb + tm + 4]);
                af[im][3] = __float_as_uint(pA[(rb + 8) * AS_STRIDE + kb + tm + 4]);
            }
            #pragma unroll
            for (int jn = 0; jn < 4; jn++) {
                int cb = wn * 32 + jn * 8 + t4;
                bf[jn][0] = __float_as_uint(pB[(kb + tm) * BS_STRIDE + cb]);
                bf[jn][1] = __float_as_uint(pB[(kb + tm + 4) * BS_STRIDE + cb]);
            }
            #pragma unroll
            for (int im = 0; im < 4; im++)
                #pragma unroll
                for (int jn = 0; jn < 4; jn++)
                    asm volatile(
                        "mma.sync.aligned.m16n8k8.row.col.f32.tf32.tf32.f32 "
                        "{%0,%1,%2,%3}, {%4,%5,%6,%7}, {%8,%9}, {%0,%1,%2,%3};\n"
                        : "+f"(acc[im][jn][0]), "+f"(acc[im][jn][1]),
                          "+f"(acc[im][jn][2]), "+f"(acc[im][jn][3])
                        : "r"(af[im][0]), "r"(af[im][1]),
                          "r"(af[im][2]), "r"(af[im][3]),
                          "r"(bf[jn][0]), "r"(bf[jn][1]));
        }
        __syncthreads();
    }

    int half = N >> 1;
    #pragma unroll
    for (int im = 0; im < 4; im++) {
        int row = bm + wm * 64 + im * 16 + t4;
        #pragma unroll
        for (int jn = 0; jn < 4; jn++) {
            int col = bn + wn * 32 + jn * 8 + 2 * tm;
            if (NGUARD && col >= N) continue;
            size_t o0 = (size_t)row * N + col;
            size_t o1 = (size_t)(row + 8) * N + col;
            float v[4] = {acc[im][jn][0], acc[im][jn][1],
                          acc[im][jn][2], acc[im][jn][3]};
            if (EPI == 2) {
                float b0 = bias[col], b1 = bias[col + 1];
                v[0] += b0; v[1] += b1; v[2] += b0; v[3] += b1;
                #pragma unroll
                for (int e = 0; e < 4; e++)
                    v[e] = (v[e] > 20.f) ? v[e] : log1pf(__expf(v[e]));
            } else if (EPI == 1) {
                if (col >= half) {
                    #pragma unroll
                    for (int e = 0; e < 4; e++)
                        v[e] = v[e] / (1.f + __expf(-v[e]));
                }
            }
            float2 v0 = make_float2(v[0], v[1]);
            float2 v1 = make_float2(v[2], v[3]);
            if (resid) {
                float2 r0 = *(const float2*)(resid + o0);
                float2 r1 = *(const float2*)(resid + o1);
                v0.x += r0.x; v0.y += r0.y;
                v1.x += r1.x; v1.y += r1.y;
            }
            *(float2*)(C + o0) = v0;
            *(float2*)(C + o1) = v1;
        }
    }
}

// ---------------- 3. depthwise causal conv (K=4) + bias + SiLU -------------
__global__ void conv_silu_kernel(const float* __restrict__ cw,
                                 const float* __restrict__ cb) {
    int idx = blockIdx.x * blockDim.x + threadIdx.x;
    if (idx >= NTOK * D_INNER) return;
    int d = idx & (D_INNER - 1);
    int tok = idx >> 11;
    int t = tok & (T_SZ - 1);
    float acc = cb[d];
    #pragma unroll
    for (int k = 0; k < D_CONV; ++k) {
        int tt = t - (D_CONV - 1) + k;
        if (tt >= 0)
            acc = fmaf(g_xr[(size_t)(tok - (D_CONV - 1) + k) * (2 * D_INNER) + d],
                       cw[d * D_CONV + k], acc);
    }
    g_u[idx] = acc / (1.f + __expf(-acc));
}

// ---------------- 6. smem-staged selective scan (res pre-silued) ------------
#define SCAN_TC 32
#define SCAN_CH 32
#define SCAN_NC (T_SZ / SCAN_TC)

__global__ __launch_bounds__(512, 1)
void scan_kernel(const float* __restrict__ A_log, const float* __restrict__ Dp) {
    __shared__ float sD[2][SCAN_TC][SCAN_CH];
    __shared__ float sU[2][SCAN_TC][SCAN_CH];
    __shared__ float sR[2][SCAN_TC][SCAN_CH];
    __shared__ float sBC[2][SCAN_TC][32];
    __shared__ float sY[SCAN_TC][SCAN_CH];

    int tid = threadIdx.x;
    int bb = blockIdx.x >> 6;
    int d0 = (blockIdx.x & 63) * SCAN_CH;
    size_t tokbase = (size_t)bb * T_SZ;

    int lidx = tid & 255;
    int li = lidx >> 3;
    int lj = (lidx & 7) << 2;
    int lgrp = tid >> 8;

    int warp = tid >> 5, lane = tid & 31;
    int ch = warp * 2 + (lane >> 4);
    int n = lane & 15;
    int dg = d0 + ch;
    float a = -__expf(A_log[dg * D_STATE + n]);
    float Dv = Dp[dg];
    float h = 0.f;

    auto issue_chunk = [&](int c, int buf) {
        size_t tok = tokbase + (size_t)c * SCAN_TC + li;
        if (lgrp == 0) {
            cpa16((uint32_t)__cvta_generic_to_shared(&sD[buf][li][lj]),
                  g_delta + tok * D_INNER + d0 + lj);
            cpa16((uint32_t)__cvta_generic_to_shared(&sU[buf][li][lj]),
                  g_u + tok * D_INNER + d0 + lj);
        } else {
            cpa16((uint32_t)__cvta_generic_to_shared(&sR[buf][li][lj]),
                  g_xr + tok * (2 * D_INNER) + D_INNER + d0 + lj);
            cpa16((uint32_t)__cvta_generic_to_shared(&sBC[buf][li][lj]),
                  g_xdbc + tok * XDBC_W + DT_RANK + lj);
        }
        cpa_commit();
    };

    issue_chunk(0, 0);

    for (int c = 0; c < SCAN_NC; ++c) {
        int buf = c & 1;
        if (c + 1 < SCAN_NC) {
            issue_chunk(c + 1, buf ^ 1);
            cpa_wait<1>();
        } else {
            cpa_wait<0>();
        }
        __syncthreads();

        #pragma unroll 4
        for (int t = 0; t < SCAN_TC; ++t) {
            float dv = sD[buf][t][ch];
            float uv = sU[buf][t][ch];
            float Bv = sBC[buf][t][n];
            float Cv = sBC[buf][t][16 + n];
            h = fmaf(__expf(dv * a), h, (dv * uv) * Bv);
            float p = h * Cv;
            p += __shfl_down_sync(0xffffffffu, p, 8, 16);
            p += __shfl_down_sync(0xffffffffu, p, 4, 16);
            p += __shfl_down_sync(0xffffffffu, p, 2, 16);
            p += __shfl_down_sync(0xffffffffu, p, 1, 16);
            if (n == 0) {
                // res already silu'd by GEMM1 epilogue
                sY[t][ch] = fmaf(uv, Dv, p) * sR[buf][t][ch];
            }
        }
        __syncthreads();

        if (lgrp == 0) {
            size_t tok = tokbase + (size_t)c * SCAN_TC + li;
            *(float4*)(g_y + tok * D_INNER + d0 + lj) = *(float4*)(&sY[li][lj]);
        }
    }
}

// ---------------- launch ----------------------------------------------------
extern "C" void kernel_launch(void* const* d_in, const int* in_sizes, int n_in,
                              void* d_out, int out_size) {
    const float* x      = (const float*)d_in[0];
    const float* norm_w = (const float*)d_in[1];
    const float* w_in   = (const float*)d_in[2];
    const float* conv_w = (const float*)d_in[3];
    const float* conv_b = (const float*)d_in[4];
    const float* w_x    = (const float*)d_in[5];
    const float* w_dt   = (const float*)d_in[6];
    const float* b_dt   = (const float*)d_in[7];
    const float* A_log  = (const float*)d_in[8];
    const float* Dp     = (const float*)d_in[9];
    const float* w_out  = (const float*)d_in[10];
    float* out = (float*)d_out;

    void *p_xn = nullptr, *p_xr = nullptr, *p_u = nullptr, *p_xdbc = nullptr,
         *p_delta = nullptr, *p_y = nullptr;
    cudaGetSymbolAddress(&p_xn, g_xn);
    cudaGetSymbolAddress(&p_xr, g_xr);
    cudaGetSymbolAddress(&p_u, g_u);
    cudaGetSymbolAddress(&p_xdbc, g_xdbc);
    cudaGetSymbolAddress(&p_delta, g_delta);
    cudaGetSymbolAddress(&p_y, g_y);

    cudaFuncSetAttribute(gemm_tf32<false, 0>,
                         cudaFuncAttributeMaxDynamicSharedMemorySize, GEMM_SMEM_BYTES);
    cudaFuncSetAttribute(gemm_tf32<false, 1>,
                         cudaFuncAttributeMaxDynamicSharedMemorySize, GEMM_SMEM_BYTES);
    cudaFuncSetAttribute(gemm_tf32<false, 2>,
                         cudaFuncAttributeMaxDynamicSharedMemorySize, GEMM_SMEM_BYTES);
    cudaFuncSetAttribute(gemm_tf32<true, 0>,
                         cudaFuncAttributeMaxDynamicSharedMemorySize, GEMM_SMEM_BYTES);

    rmsnorm_kernel<<<NTOK, 256>>>(x, norm_w);

    // xr = xn @ w_in; silu applied to res half (cols >= 2048)
    gemm_tf32<false, 1><<<dim3(2 * D_INNER / 128, NTOK / 128), 256, GEMM_SMEM_BYTES>>>(
        (const float*)p_xn, w_in, nullptr, nullptr, (float*)p_xr,
        NTOK, 2 * D_INNER, D_MODEL, D_MODEL);

    conv_silu_kernel<<<(NTOK * D_INNER + 255) / 256, 256>>>(conv_w, conv_b);

    // xdbc = u @ w_x  (8192 x 96, K=2048)
    gemm_tf32<true, 0><<<dim3(1, NTOK / 128), 256, GEMM_SMEM_BYTES>>>(
        (const float*)p_u, w_x, nullptr, nullptr, (float*)p_xdbc,
        NTOK, XDBC_W, D_INNER, D_INNER);

    // delta = softplus(dt @ w_dt + b_dt)  (8192 x 2048, K=64, A lda=96)
    gemm_tf32<false, 2><<<dim3(D_INNER / 128, NTOK / 128), 256, GEMM_SMEM_BYTES>>>(
        (const float*)p_xdbc, w_dt, nullptr, b_dt, (float*)p_delta,
        NTOK, D_INNER, DT_RANK, XDBC_W);

    scan_kernel<<<B_SZ * D_INNER / SCAN_CH, 512>>>(A_log, Dp);

    // out = y @ w_out + x  (8192 x 1024, K=2048)
    gemm_tf32<false, 0><<<dim3(D_MODEL / 128, NTOK / 128), 256, GEMM_SMEM_BYTES>>>(
        (const float*)p_y, w_out, x, nullptr, out, NTOK, D_MODEL, D_INNER, D_INNER);
}